// round 14
// baseline (speedup 1.0000x reference)
#include <cuda_runtime.h>
#include <cstdint>

#define B 8192
#define NNODE 64
#define DOBS 16
#define XROW 18
#define XLEN (B * NNODE * XROW)          // 9437184 floats (x region)
#define EPB 630                          // max edge columns per batch
#define ETOT (B * EPB)                   // 5160960 columns
#define KEY_STRIDE 640

#define SCAT_BLOCKS 512
#define SCAT_THREADS 1024
#define BPB (B / SCAT_BLOCKS)            // 16 batches per scatter block

__device__ unsigned short g_keys[(size_t)B * KEY_STRIDE];
__device__ int g_cnt[B];

// ---------------------------------------------------------------------------
// Kernel 1: fused x-write + per-batch edge keys. 128 thr/block. (unchanged)
// ---------------------------------------------------------------------------
__global__ void __launch_bounds__(128) build_edges_x(const float* __restrict__ obs,
                                                     const float* __restrict__ ego,
                                                     const float* __restrict__ other,
                                                     float* __restrict__ out) {
    int b = blockIdx.x;
    int t = threadIdx.x;              // 0..127
    int lane = t & 31, w = t >> 5;

    __shared__ float sx[64], sy[64];
    __shared__ unsigned long long skey[64];
    __shared__ int spart[128];
    __shared__ int sord[64];
    __shared__ unsigned sbits[5][2];
    __shared__ unsigned bitmap[128];       // 4096 bits: key = u*64 + v
    __shared__ int warpsum[4];

    const float4* src4 = (const float4*)(obs + (size_t)b * NNODE * DOBS);
    float* xout = out + (size_t)b * NNODE * XROW;

    float4 fa = src4[t];
    float4 fb = src4[t + 128];
    bitmap[t] = 0u;

    // extract x,y columns (row n starts at float4 index n*4)
    if ((t & 3) == 0) { sx[t >> 2] = fa.x; sy[t >> 2] = fa.y; }
    { int i = t + 128; if ((i & 3) == 0) { sx[i >> 2] = fb.x; sy[i >> 2] = fb.y; } }

    // write obs part of x directly: float4 i -> out row n=i>>2, cols 4(i&3)..+3
    {
        int n = t >> 2, q = t & 3;
        float2* p = (float2*)(xout + n * XROW + q * 4);
        p[0] = make_float2(fa.x, fa.y);
        p[1] = make_float2(fa.z, fa.w);
    }
    {
        int i = t + 128;
        int n = i >> 2, q = i & 3;
        float2* p = (float2*)(xout + n * XROW + q * 4);
        p[0] = make_float2(fb.x, fb.y);
        p[1] = make_float2(fb.z, fb.w);
    }
    // init columns 16,17
    if (t < 64) {
        float2 iv = (t == 0) ? make_float2(ego[0], ego[1])
                             : make_float2(other[0], other[1]);
        *(float2*)(xout + t * XROW + DOBS) = iv;
    }
    __syncthreads();   // sx/sy fully written

    // sortable key: x in [0,1) so float bits preserve order; tie-break by index
    if (t < 64) {
        skey[t] = (((unsigned long long)__float_as_uint(sx[t])) << 6) | (unsigned)t;
    }
    __syncthreads();

    // --- stable rank by x: 128 threads, 32 u64 compares each ---
    {
        int node = t & 63;
        int jbase = (t >> 6) * 32;
        unsigned long long ki = skey[node];
        int r = 0;
#pragma unroll
        for (int jj = 0; jj < 32; jj++) {
            r += (skey[jbase + jj] < ki);
        }
        spart[t] = r;
    }
    __syncthreads();
    if (t < 64) sord[spart[t] + spart[t + 64]] = t;
    __syncthreads();

    // --- lane masks + chain edges into bitmap ---
    bool mm[5];
    int node = 0;
    if (t < 64) {
        node = sord[t];               // node at sorted position t
        float ys = sy[node];
        const float T1 = (float)(1.0 / 3.0);
        const float T2 = (float)(2.0 / 3.0);
        bool f0 = (ys <= T1) && (ys > 0.0f);
        bool f1 = (ys > T1) && (ys <= T2);
        bool f2 = (ys >= T2) && (ys < 1.0f);
        mm[0] = f0; mm[1] = f1; mm[2] = f2; mm[3] = f0 || f1; mm[4] = f1 || f2;
#pragma unroll
        for (int m = 0; m < 5; m++) {
            unsigned bal = __ballot_sync(0xffffffffu, mm[m]);
            if (lane == 0) sbits[m][w] = bal;
        }
    }
    __syncthreads();

    if (t < 64) {
#pragma unroll
        for (int m = 0; m < 5; m++) {
            if (mm[m] && t < 63) {
                unsigned long long bits =
                    ((unsigned long long)sbits[m][1] << 32) | (unsigned long long)sbits[m][0];
                unsigned long long rest = bits >> (t + 1);
                if (rest) {
                    int nk = t + 1 + (__ffsll((long long)rest) - 1);
                    int v = sord[nk];
                    int k1 = node * 64 + v;
                    int k2 = v * 64 + node;
                    atomicOr(&bitmap[k1 >> 5], 1u << (k1 & 31));
                    atomicOr(&bitmap[k2 >> 5], 1u << (k2 & 31));
                }
            }
        }
    }
    __syncthreads();

    // --- compact: each of 128 threads owns one 32-bit bitmap word ---
    unsigned wv = bitmap[t];
    int c = __popc(wv);
    int inc = c;
#pragma unroll
    for (int d = 1; d < 32; d <<= 1) {
        int nv = __shfl_up_sync(0xffffffffu, inc, d);
        if (lane >= d) inc += nv;
    }
    if (lane == 31) warpsum[w] = inc;
    __syncthreads();
    int wpre = 0;
#pragma unroll
    for (int j = 0; j < 4; j++) wpre += (j < w) ? warpsum[j] : 0;
    int excl = inc - c + wpre;
    if (t == 0) g_cnt[b] = warpsum[0] + warpsum[1] + warpsum[2] + warpsum[3];

    unsigned short* kb = g_keys + (size_t)b * KEY_STRIDE;
    int pos = excl;
    int kbase = t * 32;
    while (wv) {
        int bit = __ffs(wv) - 1;
        wv &= (wv - 1);
        kb[pos++] = (unsigned short)(kbase + bit);
    }
}

// ---------------------------------------------------------------------------
// Kernel 2: flattened scatter with fused prefix. 512 blocks x 1024 threads.
// ---------------------------------------------------------------------------
__global__ void __launch_bounds__(SCAT_THREADS) scatter_pad(float* __restrict__ out) {
    int t = threadIdx.x;
    int lane = t & 31, w = t >> 5;
    int b0 = blockIdx.x * BPB;            // multiple of 16 -> int4-aligned

    __shared__ int red_b[32], red_t[32];
    __shared__ int cum[BPB + 1];          // local cumulative counts
    __shared__ int sh_sb, sh_tot;

    // --- fused scan: sum counts before b0, and total ---
    const int4* c4 = (const int4*)g_cnt;
    int s_before = 0, s_total = 0;
#pragma unroll
    for (int i = t; i < B / 4; i += SCAT_THREADS) {
        int4 v = c4[i];
        int sum = v.x + v.y + v.z + v.w;
        s_total += sum;
        if (i * 4 < b0) s_before += sum;   // no partial groups (b0 % 4 == 0)
    }
#pragma unroll
    for (int d = 16; d; d >>= 1) {
        s_before += __shfl_down_sync(0xffffffffu, s_before, d);
        s_total  += __shfl_down_sync(0xffffffffu, s_total, d);
    }
    if (lane == 0) { red_b[w] = s_before; red_t[w] = s_total; }
    __syncthreads();
    // warp 0: reduce 32 warp sums + local inclusive scan of 16 counts
    if (w == 0) {
        int sb = red_b[lane], stt = red_t[lane];
#pragma unroll
        for (int d = 16; d; d >>= 1) {
            sb  += __shfl_down_sync(0xffffffffu, sb, d);
            stt += __shfl_down_sync(0xffffffffu, stt, d);
        }
        sb  = __shfl_sync(0xffffffffu, sb, 0);
        stt = __shfl_sync(0xffffffffu, stt, 0);
        int c = (lane < BPB) ? g_cnt[b0 + lane] : 0;
        int inc = c;
#pragma unroll
        for (int d = 1; d < BPB; d <<= 1) {
            int nv = __shfl_up_sync(0xffffffffu, inc, d);
            if (lane >= d) inc += nv;
        }
        if (lane < BPB) cum[lane + 1] = inc;
        if (lane == 0) { cum[0] = 0; sh_sb = sb; sh_tot = stt; }
    }
    __syncthreads();

    float* src_out = out + XLEN;
    float* dst_out = out + XLEN + ETOT;

    // --- flat edge loop: contiguous coalesced stores, independent loads ---
    int sb = sh_sb;
    int tot = cum[BPB];
    for (int e = t; e < tot; e += SCAT_THREADS) {
        // find bb: largest index with cum[bb] <= e (16 entries, 4-step search)
        int lo = 0;
        if (cum[lo + 8] <= e) lo += 8;
        if (cum[lo + 4] <= e) lo += 4;
        if (cum[lo + 2] <= e) lo += 2;
        if (cum[lo + 1] <= e) lo += 1;
        int i = e - cum[lo];
        int k = g_keys[(size_t)(b0 + lo) * KEY_STRIDE + i];
        int nb = (b0 + lo) * NNODE;
        src_out[sb + e] = (float)(nb + (k >> 6));
        dst_out[sb + e] = (float)(nb + (k & 63));
    }

    // pad region [T, ETOT): contiguous run per block, float4 body
    int T = sh_tot;
    int P = ETOT - T;
    int chunk = (P + SCAT_BLOCKS - 1) / SCAT_BLOCKS;
    int start = T + blockIdx.x * chunk;
    int end = start + chunk;
    if (end > ETOT) end = ETOT;
    if (start < end) {
        int a0 = (start + 3) & ~3;
        int a1 = end & ~3;
        if (a0 > end) a0 = end;          // tiny range fallback
        if (a1 < a0) a1 = a0;
        // scalar head/tail
        if (t < a0 - start) { src_out[start + t] = -1.0f; dst_out[start + t] = -1.0f; }
        if (t < end - a1)  { src_out[a1 + t] = -1.0f;     dst_out[a1 + t] = -1.0f; }
        // vector body
        float4 m1 = make_float4(-1.0f, -1.0f, -1.0f, -1.0f);
        float4* s4 = (float4*)src_out;
        float4* d4 = (float4*)dst_out;
        for (int j = (a0 >> 2) + t; j < (a1 >> 2); j += SCAT_THREADS) {
            s4[j] = m1;
            d4[j] = m1;
        }
    }
}

// ---------------------------------------------------------------------------
extern "C" void kernel_launch(void* const* d_in, const int* in_sizes, int n_in,
                              void* d_out, int out_size) {
    const float* obs = (const float*)d_in[0];
    const float* ego = (const float*)d_in[1];
    const float* other = (const float*)d_in[2];
    float* out = (float*)d_out;

    build_edges_x<<<B, 128>>>(obs, ego, other, out);
    scatter_pad<<<SCAT_BLOCKS, SCAT_THREADS>>>(out);
}

// round 15
// speedup vs baseline: 1.0448x; 1.0448x over previous
#include <cuda_runtime.h>
#include <cstdint>

#define B 8192
#define NNODE 64
#define DOBS 16
#define XROW 18
#define XLEN (B * NNODE * XROW)          // 9437184 floats (x region)
#define EPB 630                          // max edge columns per batch
#define ETOT (B * EPB)                   // 5160960 columns
#define KEY_STRIDE 640

#define SCAT_BLOCKS 512
#define BPB (B / SCAT_BLOCKS)            // 16 batches per scatter block

__device__ unsigned short g_keys[(size_t)B * KEY_STRIDE];
__device__ int g_cnt[B];

// ---------------------------------------------------------------------------
// Kernel 1: fused x-write + per-batch edge keys. 64 thr/block, dense phases.
// ---------------------------------------------------------------------------
__global__ void __launch_bounds__(64) build_edges_x(const float* __restrict__ obs,
                                                    const float* __restrict__ ego,
                                                    const float* __restrict__ other,
                                                    float* __restrict__ out) {
    int b = blockIdx.x;
    int t = threadIdx.x;              // 0..63
    int lane = t & 31, w = t >> 5;

    __shared__ float sy[64];
    __shared__ unsigned long long skey[64];
    __shared__ int sord[64];
    __shared__ unsigned sbits[5][2];
    __shared__ unsigned bitmap[128];       // 4096 bits: key = u*64 + v
    __shared__ int warpsum[2];

    const float4* src4 = (const float4*)(obs + (size_t)b * NNODE * DOBS);
    float* xout = out + (size_t)b * NNODE * XROW;

    bitmap[t] = 0u;
    bitmap[t + 64] = 0u;

    // 4 coalesced float4 loads; write x region; chunk owners fill sy/skey
#pragma unroll
    for (int i = 0; i < 4; i++) {
        int c = i * 64 + t;               // chunk index 0..255
        float4 f = src4[c];
        int n = c >> 2, q = c & 3;
        float2* p = (float2*)(xout + n * XROW + q * 4);
        p[0] = make_float2(f.x, f.y);
        p[1] = make_float2(f.z, f.w);
        if (q == 0) {                      // this chunk holds row n's x,y
            sy[n] = f.y;
            skey[n] = (((unsigned long long)__float_as_uint(f.x)) << 6) | (unsigned)n;
        }
    }
    // init columns 16,17 (row t)
    {
        float2 iv = (t == 0) ? make_float2(ego[0], ego[1])
                             : make_float2(other[0], other[1]);
        *(float2*)(xout + t * XROW + DOBS) = iv;
    }
    __syncthreads();   // sy/skey fully written

    // --- stable rank by x: 64 u64 compares per thread ---
    {
        unsigned long long ki = skey[t];
        int r = 0;
#pragma unroll 16
        for (int j = 0; j < 64; j++) r += (skey[j] < ki);
        sord[r] = t;
    }
    __syncthreads();

    // --- lane masks over sorted positions + chain edges into bitmap ---
    int node = sord[t];               // node at sorted position t
    float ys = sy[node];
    const float T1 = (float)(1.0 / 3.0);
    const float T2 = (float)(2.0 / 3.0);
    bool f0m = (ys <= T1) && (ys > 0.0f);
    bool f1m = (ys > T1) && (ys <= T2);
    bool f2m = (ys >= T2) && (ys < 1.0f);
    bool mm[5] = { f0m, f1m, f2m, f0m || f1m, f1m || f2m };
#pragma unroll
    for (int m = 0; m < 5; m++) {
        unsigned bal = __ballot_sync(0xffffffffu, mm[m]);
        if (lane == 0) sbits[m][w] = bal;
    }
    __syncthreads();

#pragma unroll
    for (int m = 0; m < 5; m++) {
        if (mm[m] && t < 63) {
            unsigned long long bits =
                ((unsigned long long)sbits[m][1] << 32) | (unsigned long long)sbits[m][0];
            unsigned long long rest = bits >> (t + 1);
            if (rest) {
                int nk = t + 1 + (__ffsll((long long)rest) - 1);
                int v = sord[nk];
                int k1 = node * 64 + v;
                int k2 = v * 64 + node;
                atomicOr(&bitmap[k1 >> 5], 1u << (k1 & 31));
                atomicOr(&bitmap[k2 >> 5], 1u << (k2 & 31));
            }
        }
    }
    __syncthreads();

    // --- compact: thread t owns bitmap words 2t, 2t+1 ---
    uint2 bw = *(const uint2*)&bitmap[2 * t];
    unsigned w0 = bw.x, w1 = bw.y;
    int c = __popc(w0) + __popc(w1);
    int inc = c;
#pragma unroll
    for (int d = 1; d < 32; d <<= 1) {
        int nv = __shfl_up_sync(0xffffffffu, inc, d);
        if (lane >= d) inc += nv;
    }
    if (lane == 31) warpsum[w] = inc;
    __syncthreads();
    int excl = inc - c + (w ? warpsum[0] : 0);
    if (t == 0) g_cnt[b] = warpsum[0] + warpsum[1];

    unsigned short* kb = g_keys + (size_t)b * KEY_STRIDE;
    int pos = excl;
    int kbase = t * 64;
    while (w0) {
        int bit = __ffs(w0) - 1;
        w0 &= (w0 - 1);
        kb[pos++] = (unsigned short)(kbase + bit);
    }
    kbase += 32;
    while (w1) {
        int bit = __ffs(w1) - 1;
        w1 &= (w1 - 1);
        kb[pos++] = (unsigned short)(kbase + bit);
    }
}

// ---------------------------------------------------------------------------
// Kernel 2: flattened scatter with fused prefix. 512 blocks x 256 threads.
// ---------------------------------------------------------------------------
__global__ void __launch_bounds__(256) scatter_pad(float* __restrict__ out) {
    int t = threadIdx.x;
    int lane = t & 31, w = t >> 5;
    int b0 = blockIdx.x * BPB;            // multiple of 16 -> int4-aligned

    __shared__ int red_b[8], red_t[8];
    __shared__ int cum[BPB + 1];          // local cumulative counts
    __shared__ int sh_sb, sh_tot;

    // --- fused scan: sum counts before b0, and total ---
    const int4* c4 = (const int4*)g_cnt;
    int s_before = 0, s_total = 0;
#pragma unroll
    for (int i = t; i < B / 4; i += 256) {
        int4 v = c4[i];
        int sum = v.x + v.y + v.z + v.w;
        s_total += sum;
        if (i * 4 < b0) s_before += sum;   // no partial groups (b0 % 4 == 0)
    }
#pragma unroll
    for (int d = 16; d; d >>= 1) {
        s_before += __shfl_down_sync(0xffffffffu, s_before, d);
        s_total  += __shfl_down_sync(0xffffffffu, s_total, d);
    }
    if (lane == 0) { red_b[w] = s_before; red_t[w] = s_total; }
    __syncthreads();
    // warp 0: local inclusive scan of this block's 16 counts -> cum[1..16]
    if (w == 0) {
        int sb = 0, stt = 0;
#pragma unroll
        for (int j = 0; j < 8; j++) { sb += red_b[j]; stt += red_t[j]; }
        int c = (lane < BPB) ? g_cnt[b0 + lane] : 0;
        int inc = c;
#pragma unroll
        for (int d = 1; d < BPB; d <<= 1) {
            int nv = __shfl_up_sync(0xffffffffu, inc, d);
            if (lane >= d) inc += nv;
        }
        if (lane < BPB) cum[lane + 1] = inc;
        if (lane == 0) { cum[0] = 0; sh_sb = sb; sh_tot = stt; }
    }
    __syncthreads();

    float* src_out = out + XLEN;
    float* dst_out = out + XLEN + ETOT;

    // --- flat edge loop: contiguous coalesced stores, independent loads ---
    int sb = sh_sb;
    int tot = cum[BPB];
    for (int e = t; e < tot; e += 256) {
        // find bb: largest index with cum[bb] <= e (16 entries, 4-step search)
        int lo = 0;
        if (cum[lo + 8] <= e) lo += 8;
        if (cum[lo + 4] <= e) lo += 4;
        if (cum[lo + 2] <= e) lo += 2;
        if (cum[lo + 1] <= e) lo += 1;
        int i = e - cum[lo];
        int k = g_keys[(size_t)(b0 + lo) * KEY_STRIDE + i];
        int nb = (b0 + lo) * NNODE;
        src_out[sb + e] = (float)(nb + (k >> 6));
        dst_out[sb + e] = (float)(nb + (k & 63));
    }

    // pad region [T, ETOT): contiguous run per block, float4 body
    int T = sh_tot;
    int P = ETOT - T;
    int chunk = (P + SCAT_BLOCKS - 1) / SCAT_BLOCKS;
    int start = T + blockIdx.x * chunk;
    int end = start + chunk;
    if (end > ETOT) end = ETOT;
    if (start < end) {
        int a0 = (start + 3) & ~3;
        int a1 = end & ~3;
        if (a0 > end) a0 = end;          // tiny range fallback
        if (a1 < a0) a1 = a0;
        // scalar head/tail
        if (t < a0 - start) { src_out[start + t] = -1.0f; dst_out[start + t] = -1.0f; }
        if (t < end - a1)  { src_out[a1 + t] = -1.0f;     dst_out[a1 + t] = -1.0f; }
        // vector body
        float4 m1 = make_float4(-1.0f, -1.0f, -1.0f, -1.0f);
        float4* s4 = (float4*)src_out;
        float4* d4 = (float4*)dst_out;
        for (int j = (a0 >> 2) + t; j < (a1 >> 2); j += 256) {
            s4[j] = m1;
            d4[j] = m1;
        }
    }
}

// ---------------------------------------------------------------------------
extern "C" void kernel_launch(void* const* d_in, const int* in_sizes, int n_in,
                              void* d_out, int out_size) {
    const float* obs = (const float*)d_in[0];
    const float* ego = (const float*)d_in[1];
    const float* other = (const float*)d_in[2];
    float* out = (float*)d_out;

    build_edges_x<<<B, 64>>>(obs, ego, other, out);
    scatter_pad<<<SCAT_BLOCKS, 256>>>(out);
}